// round 1
// baseline (speedup 1.0000x reference)
#include <cuda_runtime.h>
#include <cstdint>
#include <cstdio>

// ---------------------------------------------------------------------------
// Problem constants (fixed shapes from reference)
// ---------------------------------------------------------------------------
#define DIN_   2048
#define NQ_    4096      // NHEAD*NGROUP*DHEAD
#define NK_    1024      // NHEAD*DHEAD
#define NTOT_  5120      // NQ_ + NK_
#define DHEAD_ 128
#define NHEAD_ 8
#define NGROUP_ 4
#define SINK_  16
#define SMAX_  32768

// Scratch (device globals are the sanctioned no-alloc workaround)
__device__ float g_qbuf[(size_t)SMAX_ * NQ_];   // 512 MB
__device__ float g_kbuf[(size_t)SMAX_ * NK_];   // 128 MB

// ---------------------------------------------------------------------------
// GEMM: C[S, 5120] = hidden[S,2048] @ [Wq;Wk]^T  (+bq on the q part)
// TF32 mma.sync.m16n8k8, BM=128 BN=128 BK=32, cp.async double buffer
// ---------------------------------------------------------------------------
#define BM 128
#define BN 128
#define BK 32
#define PAD 36                    // floats per smem row (conflict-free frag loads)
#define STAGE_FLOATS (2 * BM * PAD)   // A tile + B tile per stage
#define SMEM_BYTES (2 * STAGE_FLOATS * 4)

__device__ __forceinline__ void cp16(float* dst, const float* src) {
    uint32_t d = (uint32_t)__cvta_generic_to_shared(dst);
    asm volatile("cp.async.cg.shared.global [%0], [%1], 16;\n" :: "r"(d), "l"(src));
}

__device__ __forceinline__ uint32_t f2tf(float x) {
    uint32_t r;
    asm volatile("cvt.rna.tf32.f32 %0, %1;\n" : "=r"(r) : "f"(x));
    return r;
}

__device__ __forceinline__ void mma_tf32(float c[4], const uint32_t a[4], const uint32_t b[2]) {
    asm volatile(
        "mma.sync.aligned.m16n8k8.row.col.f32.tf32.tf32.f32 "
        "{%0,%1,%2,%3}, {%4,%5,%6,%7}, {%8,%9}, {%0,%1,%2,%3};\n"
        : "+f"(c[0]), "+f"(c[1]), "+f"(c[2]), "+f"(c[3])
        : "r"(a[0]), "r"(a[1]), "r"(a[2]), "r"(a[3]), "r"(b[0]), "r"(b[1]));
}

__device__ __forceinline__ void load_tile(float* stage, const float* Arow,
                                          const float* W, int k0, int tid) {
    float* As = stage;
    float* Bs = stage + BM * PAD;
#pragma unroll
    for (int i = 0; i < 4; i++) {
        int chunk = tid + i * 256;        // 1024 chunks of 16B cover 128x32 floats
        int r = chunk >> 3;
        int c = (chunk & 7) << 2;         // float col, multiple of 4
        cp16(As + r * PAD + c, Arow + (size_t)r * DIN_ + k0 + c);
        cp16(Bs + r * PAD + c, W + (size_t)r * DIN_ + k0 + c);
    }
}

__global__ void __launch_bounds__(256, 2) gemm_qk(
    const float* __restrict__ hidden, const float* __restrict__ Wq,
    const float* __restrict__ Wk, const float* __restrict__ bq)
{
    extern __shared__ float sm[];
    const int tid = threadIdx.x;
    const int n0 = blockIdx.x * BN;
    const int m0 = blockIdx.y * BM;
    const bool isq = (n0 < NQ_);
    const float* W = isq ? (Wq + (size_t)n0 * DIN_)
                         : (Wk + (size_t)(n0 - NQ_) * DIN_);
    const float* Arow = hidden + (size_t)m0 * DIN_;

    const int lane = tid & 31, wid = tid >> 5;
    const int wm = wid >> 2, wn = wid & 3;    // 2 x 4 warp grid; warp tile 64x32
    const int gid = lane >> 2, tig = lane & 3;

    float acc[4][4][4];
#pragma unroll
    for (int a = 0; a < 4; a++)
#pragma unroll
        for (int b = 0; b < 4; b++)
#pragma unroll
            for (int c = 0; c < 4; c++) acc[a][b][c] = 0.f;

    load_tile(sm, Arow, W, 0, tid);
    asm volatile("cp.async.commit_group;\n");

    const int NKT = DIN_ / BK;   // 64
    for (int kt = 0; kt < NKT; kt++) {
        if (kt + 1 < NKT) {
            load_tile(sm + ((kt + 1) & 1) * STAGE_FLOATS, Arow, W, (kt + 1) * BK, tid);
            asm volatile("cp.async.commit_group;\n");
            asm volatile("cp.async.wait_group 1;\n");
        } else {
            asm volatile("cp.async.wait_group 0;\n");
        }
        __syncthreads();

        const float* As = sm + (kt & 1) * STAGE_FLOATS;
        const float* Bs = As + BM * PAD;
#pragma unroll
        for (int kk = 0; kk < BK; kk += 8) {
            uint32_t af[4][4], bf[4][2];
#pragma unroll
            for (int tm = 0; tm < 4; tm++) {
                const float* ap = As + (wm * 64 + tm * 16 + gid) * PAD + kk + tig;
                af[tm][0] = f2tf(ap[0]);
                af[tm][1] = f2tf(ap[8 * PAD]);
                af[tm][2] = f2tf(ap[4]);
                af[tm][3] = f2tf(ap[8 * PAD + 4]);
            }
#pragma unroll
            for (int tn = 0; tn < 4; tn++) {
                const float* bp = Bs + (wn * 32 + tn * 8 + gid) * PAD + kk + tig;
                bf[tn][0] = f2tf(bp[0]);
                bf[tn][1] = f2tf(bp[4]);
            }
#pragma unroll
            for (int tm = 0; tm < 4; tm++)
#pragma unroll
                for (int tn = 0; tn < 4; tn++)
                    mma_tf32(acc[tm][tn], af[tm], bf[tn]);
        }
        __syncthreads();
    }

    // Store (+bias for q part)
    float* obase;
    int ld, cb;
    if (isq) { obase = g_qbuf; ld = NQ_; cb = n0; }
    else     { obase = g_kbuf; ld = NK_; cb = n0 - NQ_; }

#pragma unroll
    for (int tm = 0; tm < 4; tm++) {
#pragma unroll
        for (int tn = 0; tn < 4; tn++) {
            int r = m0 + wm * 64 + tm * 16 + gid;
            int c = cb + wn * 32 + tn * 8 + 2 * tig;
            float b0 = 0.f, b1 = 0.f;
            if (isq) { b0 = bq[c]; b1 = bq[c + 1]; }
            float2 v0 = make_float2(acc[tm][tn][0] + b0, acc[tm][tn][1] + b1);
            float2 v1 = make_float2(acc[tm][tn][2] + b0, acc[tm][tn][3] + b1);
            *reinterpret_cast<float2*>(obase + (size_t)r * ld + c) = v0;
            *reinterpret_cast<float2*>(obase + (size_t)(r + 8) * ld + c) = v1;
        }
    }
}

// ---------------------------------------------------------------------------
// Epilogue: per token -> RMSNorm(q), RMSNorm(k), logits, sink gate, mean over g
// 8 warps/block = 1 head each; k_base cached in registers; 16 tokens/block
// ---------------------------------------------------------------------------
#define TOK_PER_BLK 16

__device__ __forceinline__ float wsum(float v) {
    v += __shfl_xor_sync(0xffffffffu, v, 16);
    v += __shfl_xor_sync(0xffffffffu, v, 8);
    v += __shfl_xor_sync(0xffffffffu, v, 4);
    v += __shfl_xor_sync(0xffffffffu, v, 2);
    v += __shfl_xor_sync(0xffffffffu, v, 1);
    return v;
}

__global__ void __launch_bounds__(256) epilogue_kernel(
    float* __restrict__ out, const float* __restrict__ bvec,
    const float* __restrict__ k_base, const float* __restrict__ qw,
    const float* __restrict__ kw, int nseq)
{
    const int lane = threadIdx.x & 31;
    const int h = threadIdx.x >> 5;           // 8 warps -> 8 heads
    const float inv_d = 0.08838834764831845f; // 1/sqrt(128)

    float kb[SINK_][4];
#pragma unroll
    for (int t = 0; t < SINK_; t++)
#pragma unroll
        for (int j = 0; j < 4; j++)
            kb[t][j] = k_base[(size_t)(h * SINK_ + t) * DHEAD_ + lane + 32 * j];

    float qwr[4], kwr[4];
#pragma unroll
    for (int j = 0; j < 4; j++) {
        qwr[j] = qw[lane + 32 * j];
        kwr[j] = kw[lane + 32 * j];
    }
    float bb[4];
#pragma unroll
    for (int g = 0; g < NGROUP_; g++) bb[g] = bvec[h * NGROUP_ + g];

    for (int tt = 0; tt < TOK_PER_BLK; tt++) {
        const int s = blockIdx.x * TOK_PER_BLK + tt;

        // ---- k head: load + rmsnorm
        const float* kp = g_kbuf + (size_t)s * NK_ + h * DHEAD_;
        float kd[4], kn[4];
#pragma unroll
        for (int j = 0; j < 4; j++) kd[j] = kp[lane + 32 * j];
        float kss = kd[0]*kd[0] + kd[1]*kd[1] + kd[2]*kd[2] + kd[3]*kd[3];
        kss = wsum(kss);
        float rk = rsqrtf(kss * (1.0f / DHEAD_) + 1e-6f);
#pragma unroll
        for (int j = 0; j < 4; j++) kn[j] = kd[j] * rk * kwr[j];

        float accg = 0.f;
#pragma unroll
        for (int g = 0; g < NGROUP_; g++) {
            const float* qp = g_qbuf + (size_t)s * NQ_ + h * (NGROUP_ * DHEAD_) + g * DHEAD_;
            float qd[4], qn[4];
#pragma unroll
            for (int j = 0; j < 4; j++) qd[j] = qp[lane + 32 * j];
            float qss = qd[0]*qd[0] + qd[1]*qd[1] + qd[2]*qd[2] + qd[3]*qd[3];
            qss = wsum(qss);
            float rq = rsqrtf(qss * (1.0f / DHEAD_) + 1e-6f);
#pragma unroll
            for (int j = 0; j < 4; j++) qn[j] = qd[j] * rq * qwr[j];

            float dt = qn[0]*kn[0] + qn[1]*kn[1] + qn[2]*kn[2] + qn[3]*kn[3];
            dt = wsum(dt);
            float logit = dt * inv_d + 2.f * bb[g];

            float se = 0.f;
#pragma unroll
            for (int t = 0; t < SINK_; t++) {
                float p = kb[t][0]*qn[0] + kb[t][1]*qn[1] + kb[t][2]*qn[2] + kb[t][3]*qn[3];
                p = wsum(p);
                se += __expf(p * inv_d - logit);
            }
            accg += 1.f / (1.f + se);
        }
        if (lane == 0) out[(size_t)h * nseq + s] = 0.25f * accg;
    }
}

// ---------------------------------------------------------------------------
// Launch
// ---------------------------------------------------------------------------
extern "C" void kernel_launch(void* const* d_in, const int* in_sizes, int n_in,
                              void* d_out, int out_size)
{
    const float* hidden = (const float*)d_in[0];
    const float* Wq     = (const float*)d_in[1];
    const float* bq     = (const float*)d_in[2];
    const float* Wk     = (const float*)d_in[3];
    const float* qw     = (const float*)d_in[4];
    const float* kw     = (const float*)d_in[5];
    const float* bvec   = (const float*)d_in[6];
    const float* kbase  = (const float*)d_in[7];

    const int nseq = in_sizes[0] / DIN_;

    cudaFuncSetAttribute(gemm_qk, cudaFuncAttributeMaxDynamicSharedMemorySize, SMEM_BYTES);

    dim3 ggrid(NTOT_ / BN, nseq / BM);
    gemm_qk<<<ggrid, 256, SMEM_BYTES>>>(hidden, Wq, Wk, bq);

    epilogue_kernel<<<nseq / TOK_PER_BLK, 256>>>((float*)d_out, bvec, kbase, qw, kw, nseq);
}

// round 4
// speedup vs baseline: 1.2600x; 1.2600x over previous
#include <cuda_runtime.h>
#include <cstdint>

// ---------------------------------------------------------------------------
// Problem constants
// ---------------------------------------------------------------------------
#define DIN_   2048
#define NQ_    4096
#define NK_    1024
#define NTOT_  5120
#define DHEAD_ 128
#define NHEAD_ 8
#define NGROUP_ 4
#define SINK_  16
#define SMAX_  32768

__device__ float g_qbuf[(size_t)SMAX_ * NQ_];   // 512 MB scratch
__device__ float g_kbuf[(size_t)SMAX_ * NK_];   // 128 MB scratch

// ---------------------------------------------------------------------------
// GEMM: C[S,5120] = hidden[S,2048] @ [Wq;Wk]^T (+bq on q part)
// legacy mma.sync m16n8k8 tf32 (raw fp32 bits = truncation; RMSNorm cancels
// the uniform bias), ldmatrix fragments, BM=128 BN=256 BK=32, 3-stage ring
// ---------------------------------------------------------------------------
#define BM 128
#define BN 256
#define BK 32
#define NSTAGE 3
#define A_BYTES (128 * 128)            // 128 rows x 32 floats (128B)
#define B_BYTES (256 * 128)            // 256 rows x 32 floats
#define SLOT_BYTES (A_BYTES + B_BYTES) // 48 KB
#define SMEM_TOTAL (NSTAGE * SLOT_BYTES)

__device__ __forceinline__ uint32_t smem_to_u32(const void* p) {
    uint32_t a;
    asm("{ .reg .u64 t; cvta.to.shared.u64 t, %1; cvt.u32.u64 %0, t; }" : "=r"(a) : "l"(p));
    return a;
}

__device__ __forceinline__ void cp16s(uint32_t dst, const float* src) {
    asm volatile("cp.async.cg.shared.global [%0], [%1], 16;\n" :: "r"(dst), "l"(src));
}

__device__ __forceinline__ void ldsm_x4(uint32_t& r0, uint32_t& r1, uint32_t& r2,
                                        uint32_t& r3, uint32_t addr) {
    asm volatile("ldmatrix.sync.aligned.m8n8.x4.shared.b16 {%0,%1,%2,%3}, [%4];"
                 : "=r"(r0), "=r"(r1), "=r"(r2), "=r"(r3) : "r"(addr));
}

__device__ __forceinline__ void mma_tf32(float c[4], const uint32_t a[4],
                                         const uint32_t b0, const uint32_t b1) {
    asm volatile(
        "mma.sync.aligned.m16n8k8.row.col.f32.tf32.tf32.f32 "
        "{%0,%1,%2,%3}, {%4,%5,%6,%7}, {%8,%9}, {%0,%1,%2,%3};\n"
        : "+f"(c[0]), "+f"(c[1]), "+f"(c[2]), "+f"(c[3])
        : "r"(a[0]), "r"(a[1]), "r"(a[2]), "r"(a[3]), "r"(b0), "r"(b1));
}

// swizzled byte offset of (row, chunk); chunk = 16B unit within the 128B row
__device__ __forceinline__ uint32_t swz(int row, int chunk) {
    return (uint32_t)(row * 128 + ((chunk ^ (row & 7)) << 4));
}

__global__ void __launch_bounds__(256, 1) gemm_qk(
    const float* __restrict__ hidden, const float* __restrict__ Wq,
    const float* __restrict__ Wk, const float* __restrict__ bq)
{
    extern __shared__ char smem[];
    const uint32_t sbase = smem_to_u32(smem);
    const int tid = threadIdx.x;
    const int lane = tid & 31, wid = tid >> 5;
    const int wm = wid >> 2, wn = wid & 3;     // 2x4 warp grid, warp tile 64x64
    const int gid = lane >> 2, tig = lane & 3;

    const int n0 = blockIdx.x * BN;
    const int m0 = blockIdx.y * BM;
    const bool isq = (n0 < NQ_);
    const float* wrow = isq ? (Wq + (size_t)n0 * DIN_) : (Wk + (size_t)(n0 - NQ_) * DIN_);
    const float* arow = hidden + (size_t)m0 * DIN_;

    float acc[4][8][4];
#pragma unroll
    for (int a = 0; a < 4; a++)
#pragma unroll
        for (int b = 0; b < 8; b++)
#pragma unroll
            for (int c = 0; c < 4; c++) acc[a][b][c] = 0.f;

    // ldmatrix per-lane source rows/chunks (stage-invariant parts):
    // A x4: matrices = {rows 0-7, rows 8-15} x {chunk 2kk, 2kk+1}
    const int arow_l   = wm * 64 + (lane & 15);                    // + tm*16
    const int achunk_l = lane >> 4;                                // + 2*kk
    // B x4: matrices = {chunk 2kk, 2kk+1} x {rows 0-7, rows 8-15}
    const int brow_l   = wn * 64 + (lane & 7) + ((lane & 16) >> 1); // + np*16
    const int bchunk_l = (lane >> 3) & 1;                          // + 2*kk

    auto load_stage = [&](int s) {
        const uint32_t slot = sbase + (uint32_t)(s % NSTAGE) * SLOT_BYTES;
        const int k0 = s * BK;
#pragma unroll
        for (int i = 0; i < 4; i++) {          // A: 128 rows x 8 chunks
            int id = tid + i * 256;
            int r = id >> 3, c = id & 7;
            cp16s(slot + swz(r, c), arow + (size_t)r * DIN_ + k0 + c * 4);
        }
#pragma unroll
        for (int i = 0; i < 8; i++) {          // B: 256 rows x 8 chunks
            int id = tid + i * 256;
            int r = id >> 3, c = id & 7;
            cp16s(slot + A_BYTES + swz(r, c), wrow + (size_t)r * DIN_ + k0 + c * 4);
        }
        asm volatile("cp.async.commit_group;\n");
    };

    load_stage(0);
    load_stage(1);

    const int NSTEPS = DIN_ / BK;  // 64
    for (int s = 0; s < NSTEPS; s++) {
        if (s < NSTEPS - 1) asm volatile("cp.async.wait_group 1;\n" ::: "memory");
        else                asm volatile("cp.async.wait_group 0;\n" ::: "memory");
        __syncthreads();

        const uint32_t slot = sbase + (uint32_t)(s % NSTAGE) * SLOT_BYTES;
#pragma unroll
        for (int kk = 0; kk < 4; kk++) {       // 4 x k8 per stage
            uint32_t af[4][4], bf[4][4];
#pragma unroll
            for (int tm = 0; tm < 4; tm++)
                ldsm_x4(af[tm][0], af[tm][1], af[tm][2], af[tm][3],
                        slot + swz(arow_l + tm * 16, 2 * kk + achunk_l));
#pragma unroll
            for (int np = 0; np < 4; np++)
                ldsm_x4(bf[np][0], bf[np][1], bf[np][2], bf[np][3],
                        slot + A_BYTES + swz(brow_l + np * 16, 2 * kk + bchunk_l));
#pragma unroll
            for (int tm = 0; tm < 4; tm++)
#pragma unroll
                for (int np = 0; np < 4; np++) {
                    mma_tf32(acc[tm][2 * np],     af[tm], bf[np][0], bf[np][1]);
                    mma_tf32(acc[tm][2 * np + 1], af[tm], bf[np][2], bf[np][3]);
                }
        }

        if (s + 2 < NSTEPS) load_stage(s + 2);
    }

    // ---- store (+bq on q part)
    float bq0[8], bq1[8];
#pragma unroll
    for (int tn = 0; tn < 8; tn++) {
        int col = n0 + wn * 64 + tn * 8 + 2 * tig;
        bq0[tn] = isq ? __ldg(bq + col) : 0.f;
        bq1[tn] = isq ? __ldg(bq + col + 1) : 0.f;
    }
    float* obase = isq ? g_qbuf : g_kbuf;
    const int ld = isq ? NQ_ : NK_;
    const int cb = isq ? n0 : (n0 - NQ_);

#pragma unroll
    for (int tm = 0; tm < 4; tm++) {
#pragma unroll
        for (int tn = 0; tn < 8; tn++) {
            int r = m0 + wm * 64 + tm * 16 + gid;
            int c = cb + wn * 64 + tn * 8 + 2 * tig;
            float2 v0 = make_float2(acc[tm][tn][0] + bq0[tn], acc[tm][tn][1] + bq1[tn]);
            float2 v1 = make_float2(acc[tm][tn][2] + bq0[tn], acc[tm][tn][3] + bq1[tn]);
            *reinterpret_cast<float2*>(obase + (size_t)r * ld + c) = v0;
            *reinterpret_cast<float2*>(obase + (size_t)(r + 8) * ld + c) = v1;
        }
    }
}

// ---------------------------------------------------------------------------
// Epilogue: RMSNorm(q), RMSNorm(k), logits, sink gate, mean over groups
// multi-value butterfly reduction for the 16 sink dots
// ---------------------------------------------------------------------------
#define TOK_PER_BLK 16

__device__ __forceinline__ float wsum(float v) {
    v += __shfl_xor_sync(0xffffffffu, v, 16);
    v += __shfl_xor_sync(0xffffffffu, v, 8);
    v += __shfl_xor_sync(0xffffffffu, v, 4);
    v += __shfl_xor_sync(0xffffffffu, v, 2);
    v += __shfl_xor_sync(0xffffffffu, v, 1);
    return v;
}

__global__ void __launch_bounds__(256) epilogue_kernel(
    float* __restrict__ out, const float* __restrict__ bvec,
    const float* __restrict__ k_base, const float* __restrict__ qw,
    const float* __restrict__ kw, int nseq)
{
    const int lane = threadIdx.x & 31;
    const int h = threadIdx.x >> 5;
    const float inv_d = 0.08838834764831845f;

    float kb[SINK_][4];
#pragma unroll
    for (int t = 0; t < SINK_; t++)
#pragma unroll
        for (int j = 0; j < 4; j++)
            kb[t][j] = k_base[(size_t)(h * SINK_ + t) * DHEAD_ + lane + 32 * j];

    float qwr[4], kwr[4];
#pragma unroll
    for (int j = 0; j < 4; j++) {
        qwr[j] = qw[lane + 32 * j];
        kwr[j] = kw[lane + 32 * j];
    }
    float bb[4];
#pragma unroll
    for (int g = 0; g < NGROUP_; g++) bb[g] = bvec[h * NGROUP_ + g];

    const bool up16 = (lane & 16) != 0;
    const bool up8  = (lane & 8) != 0;
    const bool up4  = (lane & 4) != 0;
    const bool up2  = (lane & 2) != 0;

    for (int tt = 0; tt < TOK_PER_BLK; tt++) {
        const int s = blockIdx.x * TOK_PER_BLK + tt;

        const float* kp = g_kbuf + (size_t)s * NK_ + h * DHEAD_;
        float kd[4], kn[4];
#pragma unroll
        for (int j = 0; j < 4; j++) kd[j] = kp[lane + 32 * j];
        float kss = wsum(kd[0]*kd[0] + kd[1]*kd[1] + kd[2]*kd[2] + kd[3]*kd[3]);
        float rk = rsqrtf(kss * (1.0f / DHEAD_) + 1e-6f);
#pragma unroll
        for (int j = 0; j < 4; j++) kn[j] = kd[j] * rk * kwr[j];

        float accg = 0.f;
#pragma unroll
        for (int g = 0; g < NGROUP_; g++) {
            const float* qp = g_qbuf + (size_t)s * NQ_ + h * (NGROUP_ * DHEAD_) + g * DHEAD_;
            float qd[4], qn[4];
#pragma unroll
            for (int j = 0; j < 4; j++) qd[j] = qp[lane + 32 * j];
            float qss = wsum(qd[0]*qd[0] + qd[1]*qd[1] + qd[2]*qd[2] + qd[3]*qd[3]);
            float rq = rsqrtf(qss * (1.0f / DHEAD_) + 1e-6f);
#pragma unroll
            for (int j = 0; j < 4; j++) qn[j] = qd[j] * rq * qwr[j];

            float dt = wsum(qn[0]*kn[0] + qn[1]*kn[1] + qn[2]*kn[2] + qn[3]*kn[3]);
            float logit = dt * inv_d + 2.f * bb[g];

            // per-lane partials for the 16 sink dots
            float p[SINK_];
#pragma unroll
            for (int t = 0; t < SINK_; t++)
                p[t] = kb[t][0]*qn[0] + kb[t][1]*qn[1] + kb[t][2]*qn[2] + kb[t][3]*qn[3];

            // multi-value butterfly: 16 vals/lane -> 1 val/lane (t = (lane>>1)&15)
            float v8[8];
#pragma unroll
            for (int i = 0; i < 8; i++) {
                float sd  = up16 ? p[i] : p[8 + i];
                float kp2 = up16 ? p[8 + i] : p[i];
                v8[i] = kp2 + __shfl_xor_sync(0xffffffffu, sd, 16);
            }
            float v4[4];
#pragma unroll
            for (int i = 0; i < 4; i++) {
                float sd  = up8 ? v8[i] : v8[4 + i];
                float kp2 = up8 ? v8[4 + i] : v8[i];
                v4[i] = kp2 + __shfl_xor_sync(0xffffffffu, sd, 8);
            }
            float v2[2];
#pragma unroll
            for (int i = 0; i < 2; i++) {
                float sd  = up4 ? v4[i] : v4[2 + i];
                float kp2 = up4 ? v4[2 + i] : v4[i];
                v2[i] = kp2 + __shfl_xor_sync(0xffffffffu, sd, 4);
            }
            float sd1 = up2 ? v2[0] : v2[1];
            float kp1 = up2 ? v2[1] : v2[0];
            float v1 = kp1 + __shfl_xor_sync(0xffffffffu, sd1, 2);
            // v1 is summed over 16 lanes; add bit-0 partner for the full sum
            float S = v1 + __shfl_xor_sync(0xffffffffu, v1, 1);

            // one exp per lane (each sink t duplicated over 2 lanes)
            float e = __expf(S * inv_d - logit);
            float se = 0.5f * wsum(e);
            accg += 1.f / (1.f + se);
        }
        if (lane == 0) out[(size_t)h * nseq + s] = 0.25f * accg;
    }
}

// ---------------------------------------------------------------------------
// Launch
// ---------------------------------------------------------------------------
extern "C" void kernel_launch(void* const* d_in, const int* in_sizes, int n_in,
                              void* d_out, int out_size)
{
    const float* hidden = (const float*)d_in[0];
    const float* Wq     = (const float*)d_in[1];
    const float* bq     = (const float*)d_in[2];
    const float* Wk     = (const float*)d_in[3];
    const float* qw     = (const float*)d_in[4];
    const float* kw     = (const float*)d_in[5];
    const float* bvec   = (const float*)d_in[6];
    const float* kbase  = (const float*)d_in[7];

    const int nseq = in_sizes[0] / DIN_;

    cudaFuncSetAttribute(gemm_qk, cudaFuncAttributeMaxDynamicSharedMemorySize, SMEM_TOTAL);

    dim3 ggrid(NTOT_ / BN, nseq / BM);   // 20 x 256
    gemm_qk<<<ggrid, 256, SMEM_TOTAL>>>(hidden, Wq, Wk, bq);

    epilogue_kernel<<<nseq / TOK_PER_BLK, 256>>>((float*)d_out, bvec, kbase, qw, kw, nseq);
}